// round 4
// baseline (speedup 1.0000x reference)
#include <cuda_runtime.h>
#include <cstdint>
#include <cstddef>

// Problem dimensions
#define TT 1024
#define BB 64
#define DD 256
#define HH 512
#define H3 1536
#define OO 256

// ---------------------------------------------------------------------------
// Scratch (device globals: no allocation allowed in kernel_launch)
// ---------------------------------------------------------------------------
__device__ float g_xg[(size_t)TT * BB * H3];   // precomputed x@Wi + bi   (402 MB)
__device__ float g_hs[(size_t)TT * BB * HH];   // all hidden states      (134 MB)
__device__ unsigned int g_bar[8];              // per-batch-row barrier counters

__global__ void reset_kernel() {
    if (threadIdx.x < 8) g_bar[threadIdx.x] = 0u;
}

__device__ __forceinline__ float fast_tanh(float x) {
    float y;
    asm("tanh.approx.f32 %0, %1;" : "=f"(y) : "f"(x));
    return y;
}
__device__ __forceinline__ float fast_sigmoid(float x) {
    return 0.5f * fast_tanh(0.5f * x) + 0.5f;
}

// ---------------------------------------------------------------------------
// fp32 tiled GEMM with bias: C[M,N] = A[M,K] @ B[K,N] + bias[N]
// BM=128, BN=64, BK=16, TM=8, TN=4, 256 threads. All dims divide evenly here.
// ---------------------------------------------------------------------------
__global__ __launch_bounds__(256)
void sgemm_bias(const float* __restrict__ A, const float* __restrict__ Bw,
                const float* __restrict__ bias, float* __restrict__ C,
                int M, int N, int K)
{
    constexpr int BM = 128, BN = 64, BK = 16, TM = 8, TN = 4;
    __shared__ float As[BK][BM + 4];   // transposed A tile, padded
    __shared__ float Bs[BK][BN];

    const int tid = threadIdx.x;
    const int tx  = tid % (BN / TN);   // 0..15  (column group)
    const int ty  = tid / (BN / TN);   // 0..15  (row group)
    const int m0  = blockIdx.y * BM;
    const int n0  = blockIdx.x * BN;

    float acc[TM][TN];
#pragma unroll
    for (int i = 0; i < TM; i++)
#pragma unroll
        for (int j = 0; j < TN; j++) acc[i][j] = 0.0f;

    // load mappings
    const int a_row = tid / (BK / 4);        // 0..63
    const int a_c4  = (tid % (BK / 4)) * 4;  // 0,4,8,12
    const int b_row = tid / (BN / 4);        // 0..15
    const int b_c4  = (tid % (BN / 4)) * 4;  // 0..60

    for (int k0 = 0; k0 < K; k0 += BK) {
        // A tile: 128x16, transposed into As[k][m]
#pragma unroll
        for (int rr = 0; rr < BM; rr += 64) {
            float4 va = *(const float4*)(A + (size_t)(m0 + a_row + rr) * K + k0 + a_c4);
            As[a_c4 + 0][a_row + rr] = va.x;
            As[a_c4 + 1][a_row + rr] = va.y;
            As[a_c4 + 2][a_row + rr] = va.z;
            As[a_c4 + 3][a_row + rr] = va.w;
        }
        // B tile: 16x64
        {
            float4 vb = *(const float4*)(Bw + (size_t)(k0 + b_row) * N + n0 + b_c4);
            *(float4*)&Bs[b_row][b_c4] = vb;
        }
        __syncthreads();

#pragma unroll
        for (int kk = 0; kk < BK; kk++) {
            float af[TM], bf[TN];
#pragma unroll
            for (int i = 0; i < TM; i += 4) {
                float4 v = *(const float4*)&As[kk][ty * TM + i];
                af[i] = v.x; af[i + 1] = v.y; af[i + 2] = v.z; af[i + 3] = v.w;
            }
            {
                float4 v = *(const float4*)&Bs[kk][tx * TN];
                bf[0] = v.x; bf[1] = v.y; bf[2] = v.z; bf[3] = v.w;
            }
#pragma unroll
            for (int i = 0; i < TM; i++)
#pragma unroll
                for (int j = 0; j < TN; j++)
                    acc[i][j] += af[i] * bf[j];
        }
        __syncthreads();
    }

    // epilogue: bias + store
    float4 bv = *(const float4*)(bias + n0 + tx * TN);
#pragma unroll
    for (int i = 0; i < TM; i++) {
        float4 v;
        v.x = acc[i][0] + bv.x;
        v.y = acc[i][1] + bv.y;
        v.z = acc[i][2] + bv.z;
        v.w = acc[i][3] + bv.w;
        *(float4*)(C + (size_t)(m0 + ty * TM + i) * N + n0 + tx * TN) = v;
    }
}

// ---------------------------------------------------------------------------
// Persistent GRU recurrence.
// Grid (16, 8): blockIdx.y = batch group (8 batches), blockIdx.x = j group
// (32 hidden columns, all 3 gates). Wh slice lives in SMEM for the whole
// kernel. Per step: 3 dot products (K=512) per thread, gate math, write
// h_new, per-row barrier (16 blocks), restage h (16KB) from L2.
// ---------------------------------------------------------------------------
#define WH_STRIDE 516   // 512 + 4 pad: conflict-free float4 LDS across lanes
#define SMEM_FLOATS (3 * 32 * WH_STRIDE + 8 * HH + 32)

__global__ __launch_bounds__(256, 1)
void rnn_kernel(const float* __restrict__ Wh, const float* __restrict__ bhn,
                const float* __restrict__ h0)
{
    extern __shared__ float sm[];
    float* sm_wh  = sm;                        // [3][32][WH_STRIDE]
    float* sm_h   = sm + 3 * 32 * WH_STRIDE;   // [8][512]
    float* sm_bhn = sm_h + 8 * HH;             // [32]

    const int tid   = threadIdx.x;
    const int jl    = tid & 31;    // lane = j within group  (warp = one batch)
    const int bl    = tid >> 5;    // warp = local batch 0..7
    const int jg    = blockIdx.x;  // 0..15
    const int bg    = blockIdx.y;  // 0..7
    const int jglob = jg * 32 + jl;
    const int bglob = bg * 8 + bl;

    // --- one-time loads -----------------------------------------------------
    // Wh slice: sm_wh[g][j][k] = Wh[k][g*H + jg*32 + j]  (coalesced over j)
    for (int idx = tid; idx < 3 * 32 * HH; idx += 256) {
        int j = idx & 31;
        int k = (idx >> 5) & (HH - 1);
        int g = idx >> 14;  // idx / (32*512)
        sm_wh[(g * 32 + j) * WH_STRIDE + k] = Wh[(size_t)k * H3 + g * HH + jg * 32 + j];
    }
    if (tid < 32) sm_bhn[tid] = bhn[jg * 32 + tid];
    // stage h0 for our 8 batches
    {
        const float4* src = (const float4*)(h0 + (size_t)bg * 8 * HH);
        float4* dst = (float4*)sm_h;
        for (int i = tid; i < 8 * HH / 4; i += 256) dst[i] = src[i];
    }
    __syncthreads();

    const float* wr = sm_wh + (0 * 32 + jl) * WH_STRIDE;
    const float* wz = sm_wh + (1 * 32 + jl) * WH_STRIDE;
    const float* wn = sm_wh + (2 * 32 + jl) * WH_STRIDE;
    const float* hb = sm_h + bl * HH;
    const float  bnj = sm_bhn[jl];

    for (int step = 0; step < TT; ++step) {
        // prefetch xg for this step (overlaps with the dot products)
        const float* xgp = g_xg + ((size_t)step * BB + bglob) * H3;
        float xr = xgp[jglob];
        float xz = xgp[HH + jglob];
        float xn = xgp[2 * HH + jglob];

        float ar0 = 0.f, ar1 = 0.f, az0 = 0.f, az1 = 0.f, an0 = 0.f, an1 = 0.f;
#pragma unroll 8
        for (int k = 0; k < HH; k += 4) {
            float4 hv = *(const float4*)(hb + k);   // broadcast across warp
            float4 v;
            v = *(const float4*)(wr + k);
            ar0 += hv.x * v.x + hv.y * v.y;
            ar1 += hv.z * v.z + hv.w * v.w;
            v = *(const float4*)(wz + k);
            az0 += hv.x * v.x + hv.y * v.y;
            az1 += hv.z * v.z + hv.w * v.w;
            v = *(const float4*)(wn + k);
            an0 += hv.x * v.x + hv.y * v.y;
            an1 += hv.z * v.z + hv.w * v.w;
        }

        float r = fast_sigmoid(xr + ar0 + ar1);
        float z = fast_sigmoid(xz + az0 + az1);
        float n = fast_tanh(xn + r * ((an0 + an1) + bnj));
        float hprev = hb[jglob];
        float hnew = (1.0f - z) * n + z * hprev;
        g_hs[((size_t)step * BB + bglob) * HH + jglob] = hnew;

        // --- per-row barrier (16 blocks share this batch group) -------------
        __threadfence();
        __syncthreads();
        if (tid == 0) {
            atomicAdd(&g_bar[bg], 1u);
            const unsigned target = (unsigned)(16 * (step + 1));
            while (*((volatile unsigned*)&g_bar[bg]) < target) { }
            __threadfence();
        }
        __syncthreads();

        // restage h for our 8 batches (fresh addresses each step -> L2 hit,
        // never stale in L1)
        if (step < TT - 1) {
            const float4* src = (const float4*)(g_hs + ((size_t)step * BB + bg * 8) * HH);
            float4* dst = (float4*)sm_h;
            for (int i = tid; i < 8 * HH / 4; i += 256) dst[i] = src[i];
            __syncthreads();
        }
    }
}

// ---------------------------------------------------------------------------
// Launch: reset barrier -> xg GEMM -> persistent recurrence -> readout GEMM
// ---------------------------------------------------------------------------
extern "C" void kernel_launch(void* const* d_in, const int* in_sizes, int n_in,
                              void* d_out, int out_size)
{
    const float* x   = (const float*)d_in[0];  // [T,B,D]
    const float* Wi  = (const float*)d_in[1];  // [D,3H]
    const float* bi  = (const float*)d_in[2];  // [3H]
    const float* Wh  = (const float*)d_in[3];  // [H,3H]
    const float* bhn = (const float*)d_in[4];  // [H]
    const float* Wo  = (const float*)d_in[5];  // [H,O]
    const float* bo  = (const float*)d_in[6];  // [O]
    const float* h0  = (const float*)d_in[7];  // [B,H]
    float* out = (float*)d_out;                // [T,B,O]

    (void)in_sizes; (void)n_in; (void)out_size;

    float* xg_ptr = nullptr;
    float* hs_ptr = nullptr;
    cudaGetSymbolAddress((void**)&xg_ptr, g_xg);
    cudaGetSymbolAddress((void**)&hs_ptr, g_hs);

    const int smem_bytes = SMEM_FLOATS * (int)sizeof(float);  // 214,656 B
    cudaFuncSetAttribute(rnn_kernel, cudaFuncAttributeMaxDynamicSharedMemorySize,
                         smem_bytes);

    reset_kernel<<<1, 32>>>();

    // xg = x @ Wi + bi : M=65536, N=1536, K=256
    {
        dim3 grid(H3 / 64, (TT * BB) / 128);
        sgemm_bias<<<grid, 256>>>(x, Wi, bi, xg_ptr, TT * BB, H3, DD);
    }

    // sequential recurrence (128 co-resident blocks, 1 per SM)
    {
        dim3 grid(16, 8);
        rnn_kernel<<<grid, 256, smem_bytes>>>(Wh, bhn, h0);
    }

    // out = hs @ Wo + bo : M=65536, N=256, K=512
    {
        dim3 grid(OO / 64, (TT * BB) / 128);
        sgemm_bias<<<grid, 256>>>(hs_ptr, Wo, bo, out, TT * BB, OO, HH);
    }
}

// round 7
// speedup vs baseline: 1.8025x; 1.8025x over previous
#include <cuda_runtime.h>
#include <cstdint>
#include <cstddef>

// Problem dimensions
#define TT 1024
#define BB 64
#define DD 256
#define HH 512
#define H3 1536
#define OO 256

// ---------------------------------------------------------------------------
// Scratch (device globals: no allocation allowed in kernel_launch)
// ---------------------------------------------------------------------------
__device__ float g_xg[(size_t)TT * BB * H3];   // precomputed x@Wi + bi
__device__ float g_hs[(size_t)TT * BB * HH];   // all hidden states
__device__ unsigned int g_bar[8];              // per-batch-row barrier counters

__global__ void reset_kernel() {
    if (threadIdx.x < 8) g_bar[threadIdx.x] = 0u;
}

__device__ __forceinline__ float fast_tanh(float x) {
    float y;
    asm("tanh.approx.f32 %0, %1;" : "=f"(y) : "f"(x));
    return y;
}
__device__ __forceinline__ float fast_sigmoid(float x) {
    return 0.5f * fast_tanh(0.5f * x) + 0.5f;
}

// Packed dual fp32 FMA (Blackwell f32x2 path; PTX-only, ptxas won't auto-fuse)
__device__ __forceinline__ void ffma2(unsigned long long& d,
                                      unsigned long long a,
                                      unsigned long long b) {
    asm("fma.rn.f32x2 %0, %1, %2, %0;" : "+l"(d) : "l"(a), "l"(b));
}
__device__ __forceinline__ float f2sum(unsigned long long v) {
    float lo = __uint_as_float((unsigned)v);
    float hi = __uint_as_float((unsigned)(v >> 32));
    return lo + hi;
}

// ---------------------------------------------------------------------------
// fp32 tiled GEMM with bias: C[M,N] = A[M,K] @ B[K,N] + bias[N]
// BM=128, BN=64, BK=16, TM=8, TN=4, 256 threads. (known-good from R4)
// ---------------------------------------------------------------------------
__global__ __launch_bounds__(256)
void sgemm_bias(const float* __restrict__ A, const float* __restrict__ Bw,
                const float* __restrict__ bias, float* __restrict__ C,
                int M, int N, int K)
{
    constexpr int BM = 128, BN = 64, BK = 16, TM = 8, TN = 4;
    __shared__ float As[BK][BM + 4];
    __shared__ float Bs[BK][BN];

    const int tid = threadIdx.x;
    const int tx  = tid % (BN / TN);
    const int ty  = tid / (BN / TN);
    const int m0  = blockIdx.y * BM;
    const int n0  = blockIdx.x * BN;

    float acc[TM][TN];
#pragma unroll
    for (int i = 0; i < TM; i++)
#pragma unroll
        for (int j = 0; j < TN; j++) acc[i][j] = 0.0f;

    const int a_row = tid / (BK / 4);
    const int a_c4  = (tid % (BK / 4)) * 4;
    const int b_row = tid / (BN / 4);
    const int b_c4  = (tid % (BN / 4)) * 4;

    for (int k0 = 0; k0 < K; k0 += BK) {
#pragma unroll
        for (int rr = 0; rr < BM; rr += 64) {
            float4 va = *(const float4*)(A + (size_t)(m0 + a_row + rr) * K + k0 + a_c4);
            As[a_c4 + 0][a_row + rr] = va.x;
            As[a_c4 + 1][a_row + rr] = va.y;
            As[a_c4 + 2][a_row + rr] = va.z;
            As[a_c4 + 3][a_row + rr] = va.w;
        }
        {
            float4 vb = *(const float4*)(Bw + (size_t)(k0 + b_row) * N + n0 + b_c4);
            *(float4*)&Bs[b_row][b_c4] = vb;
        }
        __syncthreads();

#pragma unroll
        for (int kk = 0; kk < BK; kk++) {
            float af[TM], bf[TN];
#pragma unroll
            for (int i = 0; i < TM; i += 4) {
                float4 v = *(const float4*)&As[kk][ty * TM + i];
                af[i] = v.x; af[i + 1] = v.y; af[i + 2] = v.z; af[i + 3] = v.w;
            }
            {
                float4 v = *(const float4*)&Bs[kk][tx * TN];
                bf[0] = v.x; bf[1] = v.y; bf[2] = v.z; bf[3] = v.w;
            }
#pragma unroll
            for (int i = 0; i < TM; i++)
#pragma unroll
                for (int j = 0; j < TN; j++)
                    acc[i][j] += af[i] * bf[j];
        }
        __syncthreads();
    }

    float4 bv = *(const float4*)(bias + n0 + tx * TN);
#pragma unroll
    for (int i = 0; i < TM; i++) {
        float4 v;
        v.x = acc[i][0] + bv.x;
        v.y = acc[i][1] + bv.y;
        v.z = acc[i][2] + bv.z;
        v.w = acc[i][3] + bv.w;
        *(float4*)(C + (size_t)(m0 + ty * TM + i) * N + n0 + tx * TN) = v;
    }
}

// ---------------------------------------------------------------------------
// Persistent GRU recurrence, v2.
// Grid (16, 8): blockIdx.x = j group (32 columns, 3 gates), blockIdx.y =
// batch group (8 batches). Wh slice (192KB) resident in SMEM all kernel.
//
// Per step: warps split K (warp w handles k in [64w, 64w+64) for ALL 8
// batches) so each weight is read from SMEM exactly once per step; 24
// f32x2 accumulators per thread (3 gates x 8 batches, packed over k
// even/odd); 8-way cross-warp reduction via a 24KB SMEM buffer aliased
// over the h staging region; gate math distributed (thread = (batch, j));
// per-row atomic barrier across the 16 blocks sharing the batch group;
// restage h (16KB) from L2.
// ---------------------------------------------------------------------------
#define WH_STRIDE 516   // 512 + 4 pad: conflict-free LDS.128 across lanes
#define RED_FLOATS (3 * 8 * 8 * 32)              // 6144 (h staging uses first 4096)
#define SMEM_FLOATS (3 * 32 * WH_STRIDE + RED_FLOATS + 32)

__global__ __launch_bounds__(256, 1)
void rnn_kernel(const float* __restrict__ Wh, const float* __restrict__ bhn,
                const float* __restrict__ h0)
{
    extern __shared__ float sm[];
    float* sm_wh  = sm;                          // [3][32][WH_STRIDE]
    float* sm_red = sm + 3 * 32 * WH_STRIDE;     // 6144 floats; h staged in first 4096
    float* sm_bhn = sm_red + RED_FLOATS;         // [32]

    const int tid   = threadIdx.x;
    const int jl    = tid & 31;    // lane = j within group
    const int w     = tid >> 5;    // warp: k-split index (also consumer batch)
    const int jg    = blockIdx.x;  // 0..15
    const int bg    = blockIdx.y;  // 0..7
    const int jglob = jg * 32 + jl;
    const int bglob = bg * 8 + w;  // consumer-role batch

    // --- one-time loads -----------------------------------------------------
    for (int idx = tid; idx < 3 * 32 * HH; idx += 256) {
        int j = idx & 31;
        int k = (idx >> 5) & (HH - 1);
        int g = idx >> 14;
        sm_wh[(g * 32 + j) * WH_STRIDE + k] = Wh[(size_t)k * H3 + g * HH + jg * 32 + j];
    }
    if (tid < 32) sm_bhn[tid] = bhn[jg * 32 + tid];
    {
        const float4* src = (const float4*)(h0 + (size_t)bg * 8 * HH);
        float4* dst = (float4*)sm_red;
#pragma unroll
        for (int i = 0; i < 4; ++i) dst[tid + 256 * i] = src[tid + 256 * i];
    }
    __syncthreads();

    const float* wrp = sm_wh + (0 * 32 + jl) * WH_STRIDE + w * 64;
    const float* wzp = sm_wh + (1 * 32 + jl) * WH_STRIDE + w * 64;
    const float* wnp = sm_wh + (2 * 32 + jl) * WH_STRIDE + w * 64;
    const float  bnj = sm_bhn[jl];

    for (int step = 0; step < TT; ++step) {
        // prefetch xg for the consumer role (in flight during dot phase)
        const float* xgp = g_xg + ((size_t)step * BB + bglob) * H3;
        float xr = xgp[jglob];
        float xz = xgp[HH + jglob];
        float xn = xgp[2 * HH + jglob];

        // --- dot phase: this warp's 64-wide k slice, all 8 batches ----------
        unsigned long long ar[8], az[8], an[8];
#pragma unroll
        for (int b = 0; b < 8; ++b) { ar[b] = 0ull; az[b] = 0ull; an[b] = 0ull; }

        const float* hbase = sm_red + w * 64;
#pragma unroll 2
        for (int c = 0; c < 16; ++c) {
            const int k = c * 4;
            ulonglong2 wv_r = *(const ulonglong2*)(wrp + k);
            ulonglong2 wv_z = *(const ulonglong2*)(wzp + k);
            ulonglong2 wv_n = *(const ulonglong2*)(wnp + k);
#pragma unroll
            for (int b = 0; b < 8; ++b) {
                ulonglong2 hv = *(const ulonglong2*)(hbase + b * HH + k); // broadcast
                ffma2(ar[b], wv_r.x, hv.x); ffma2(ar[b], wv_r.y, hv.y);
                ffma2(az[b], wv_z.x, hv.x); ffma2(az[b], wv_z.y, hv.y);
                ffma2(an[b], wv_n.x, hv.x); ffma2(an[b], wv_n.y, hv.y);
            }
        }

        __syncthreads();                                 // all h reads done
        float hprev = sm_red[w * HH + jglob];            // consumer snapshot
        __syncthreads();                                 // before clobbering

        // --- partials to SMEM: layout [(g*8+b)*8 + w][jl], coalesced --------
#pragma unroll
        for (int b = 0; b < 8; ++b) {
            sm_red[((0  + b) * 8 + w) * 32 + jl] = f2sum(ar[b]);
            sm_red[((8  + b) * 8 + w) * 32 + jl] = f2sum(az[b]);
            sm_red[((16 + b) * 8 + w) * 32 + jl] = f2sum(an[b]);
        }
        __syncthreads();

        // --- consumer: sum 8 partials per gate, gate math -------------------
        float sr = 0.f, sz = 0.f, sn = 0.f;
#pragma unroll
        for (int ww = 0; ww < 8; ++ww) {
            sr += sm_red[((0  + w) * 8 + ww) * 32 + jl];
            sz += sm_red[((8  + w) * 8 + ww) * 32 + jl];
            sn += sm_red[((16 + w) * 8 + ww) * 32 + jl];
        }
        float r = fast_sigmoid(xr + sr);
        float z = fast_sigmoid(xz + sz);
        float n = fast_tanh(xn + r * (sn + bnj));
        float hnew = (1.0f - z) * n + z * hprev;
        g_hs[((size_t)step * BB + bglob) * HH + jglob] = hnew;

        // --- per-row barrier (16 blocks share this batch group) -------------
        __threadfence();
        __syncthreads();
        if (tid == 0) {
            atomicAdd(&g_bar[bg], 1u);
            const unsigned target = (unsigned)(16 * (step + 1));
            while (*((volatile unsigned*)&g_bar[bg]) < target) {
                __nanosleep(32);
            }
            __threadfence();
        }
        __syncthreads();

        // --- restage h for our 8 batches (fresh addresses -> L2 hit) --------
        if (step < TT - 1) {
            const float4* src = (const float4*)(g_hs + ((size_t)step * BB + bg * 8) * HH);
            float4* dst = (float4*)sm_red;
#pragma unroll
            for (int i = 0; i < 4; ++i) dst[tid + 256 * i] = src[tid + 256 * i];
            __syncthreads();
        }
    }
}

// ---------------------------------------------------------------------------
// Launch: reset barrier -> xg GEMM -> persistent recurrence -> readout GEMM
// ---------------------------------------------------------------------------
extern "C" void kernel_launch(void* const* d_in, const int* in_sizes, int n_in,
                              void* d_out, int out_size)
{
    const float* x   = (const float*)d_in[0];  // [T,B,D]
    const float* Wi  = (const float*)d_in[1];  // [D,3H]
    const float* bi  = (const float*)d_in[2];  // [3H]
    const float* Wh  = (const float*)d_in[3];  // [H,3H]
    const float* bhn = (const float*)d_in[4];  // [H]
    const float* Wo  = (const float*)d_in[5];  // [H,O]
    const float* bo  = (const float*)d_in[6];  // [O]
    const float* h0  = (const float*)d_in[7];  // [B,H]
    float* out = (float*)d_out;                // [T,B,O]

    (void)in_sizes; (void)n_in; (void)out_size;

    float* xg_ptr = nullptr;
    float* hs_ptr = nullptr;
    cudaGetSymbolAddress((void**)&xg_ptr, g_xg);
    cudaGetSymbolAddress((void**)&hs_ptr, g_hs);

    const int smem_bytes = SMEM_FLOATS * (int)sizeof(float);  // ~222.9 KB
    cudaFuncSetAttribute(rnn_kernel, cudaFuncAttributeMaxDynamicSharedMemorySize,
                         smem_bytes);

    reset_kernel<<<1, 32>>>();

    // xg = x @ Wi + bi : M=65536, N=1536, K=256
    {
        dim3 grid(H3 / 64, (TT * BB) / 128);
        sgemm_bias<<<grid, 256>>>(x, Wi, bi, xg_ptr, TT * BB, H3, DD);
    }

    // sequential recurrence (128 co-resident blocks, 1 per SM)
    {
        dim3 grid(16, 8);
        rnn_kernel<<<grid, 256, smem_bytes>>>(Wh, bhn, h0);
    }

    // out = hs @ Wo + bo : M=65536, N=256, K=512
    {
        dim3 grid(OO / 64, (TT * BB) / 128);
        sgemm_bias<<<grid, 256>>>(hs_ptr, Wo, bo, out, TT * BB, OO, HH);
    }
}